// round 12
// baseline (speedup 1.0000x reference)
#include <cuda_runtime.h>

// HGCNLayer: KG scatter-mean + sparse user aggregation.
// Inputs (JAX default config: "int64" arrays are int32):
//  0: entity_emb float32 [N_ENT*128], 1: edge_index int32 [2*E],
//  2: edge_type int32 [E], 3: interact_rows int32 [NNZ],
//  4: interact_cols int32 [NNZ], 5: interact_vals float32 [NNZ],
//  (optional n_users scalar), last: weight float32 [R*128]
// Output: [entity_agg (N_ENT*128) | user_agg (N_USR*128)] float32
//
// Counts-first: pass 1 counts edges per head; the scatter kernel computes
// inv = 1/max(count,1) inline (no invert pass, no finalize pass) and
// pre-scales each edge contribution before the red.v4.
// Scatter is one persistent wave of 1184 blocks (8/SM x 148); the section
// split is by bid/148 so every SM hosts a proportional 3:5 edge:user mix
// (classic placement maps bid%148 -> SM).

#define DD 128
#define MAX_ENTITIES 100000
#define MAX_RELS 32

__device__ float g_counts[MAX_ENTITIES];

__device__ __forceinline__ void red_add_v4(float* p, float4 v) {
    asm volatile("red.global.add.v4.f32 [%0], {%1, %2, %3, %4};"
                 :: "l"(p), "f"(v.x), "f"(v.y), "f"(v.z), "f"(v.w)
                 : "memory");
}

__device__ __forceinline__ void red_add_f32(float* p, float v) {
    asm volatile("red.global.add.f32 [%0], %1;" :: "l"(p), "f"(v) : "memory");
}

// Pass 1: per-head edge counts. int4-vectorized index load, 4 edges/thread.
__global__ void hgcn_count_kernel(const int* __restrict__ edge_index, int n_edges) {
    int t = blockIdx.x * blockDim.x + threadIdx.x;
    int base = t * 4;
    if (base + 3 < n_edges) {
        int4 h = __ldg((const int4*)(edge_index) + t);
        red_add_f32(&g_counts[h.x], 1.0f);
        red_add_f32(&g_counts[h.y], 1.0f);
        red_add_f32(&g_counts[h.z], 1.0f);
        red_add_f32(&g_counts[h.w], 1.0f);
    } else {
        for (int e = base; e < n_edges; e++)
            red_add_f32(&g_counts[edge_index[e]], 1.0f);
    }
}

// Fused scatter kernel, persistent single wave.
// Section by wave-row (bid/148): rows [0,edge_rows) = edges, rest = users.
__global__ void hgcn_scatter_kernel(const float* __restrict__ emb,
                                    const int* __restrict__ edge_index,
                                    const int* __restrict__ edge_type,
                                    const float* __restrict__ weight,
                                    const int* __restrict__ rows,
                                    const int* __restrict__ cols,
                                    const float* __restrict__ vals,
                                    float* __restrict__ ent_out,
                                    float* __restrict__ user_out,
                                    int n_edges, int n_rel, int nnz,
                                    int sms, int edge_rows, int total_rows) {
    __shared__ float4 sw[MAX_RELS * 32];
    int lane = threadIdx.x & 31;
    int wib  = threadIdx.x >> 5;
    int wpb  = blockDim.x >> 5;

    int row = blockIdx.x / sms;   // wave row on this SM
    int col = blockIdx.x % sms;   // SM index

    if (row < edge_rows) {
        // ---- edge section ----
        int nw4 = n_rel * 32;
        for (int i = threadIdx.x; i < nw4; i += blockDim.x)
            sw[i] = ((const float4*)weight)[i];
        __syncthreads();

        int eb     = row * sms + col;          // edge-block rank: 0..edge_blocks-1
        int warp   = eb * wpb + wib;
        int nwarps = edge_rows * sms * wpb;
        long stride = (long)nwarps * 2;

        for (long e0 = (long)warp * 2; e0 < n_edges; e0 += stride) {
            long e1 = e0 + 1;
            bool has1 = e1 < n_edges;

            int h0 = edge_index[e0];
            int t0 = edge_index[n_edges + e0];
            int r0 = edge_type[e0] - 1;
            int h1 = 0, t1 = 0, r1 = 0;
            if (has1) {
                h1 = edge_index[e1];
                t1 = edge_index[n_edges + e1];
                r1 = edge_type[e1] - 1;
            }

            float4 a0 = __ldg((const float4*)(emb + (long)t0 * DD) + lane);
            float4 a1 = make_float4(0.f, 0.f, 0.f, 0.f);
            if (has1) a1 = __ldg((const float4*)(emb + (long)t1 * DD) + lane);
            float inv0 = __frcp_rn(fmaxf(g_counts[h0], 1.0f));
            float inv1 = has1 ? __frcp_rn(fmaxf(g_counts[h1], 1.0f)) : 0.f;

            float4 b0 = sw[r0 * 32 + lane];
            float4 v0 = make_float4(a0.x * b0.x * inv0, a0.y * b0.y * inv0,
                                    a0.z * b0.z * inv0, a0.w * b0.w * inv0);
            red_add_v4(ent_out + (long)h0 * DD + lane * 4, v0);
            if (has1) {
                float4 b1 = sw[r1 * 32 + lane];
                float4 v1 = make_float4(a1.x * b1.x * inv1, a1.y * b1.y * inv1,
                                        a1.z * b1.z * inv1, a1.w * b1.w * inv1);
                red_add_v4(ent_out + (long)h1 * DD + lane * 4, v1);
            }
        }
    } else {
        // ---- user section: 4 nnz per warp-iteration ----
        int ub     = (row - edge_rows) * sms + col;  // user-block rank
        int user_blocks = (total_rows - edge_rows) * sms;
        int warp   = ub * wpb + wib;
        int nwarps = user_blocks * wpb;
        long stride = (long)nwarps * 4;

        for (long base = (long)warp * 4; base < nnz; base += stride) {
            int cnt = (int)min((long)4, (long)nnz - base);

            int   u[4], c[4];
            float s[4];
            #pragma unroll
            for (int j = 0; j < 4; j++) {
                long i = base + ((j < cnt) ? j : 0);
                u[j] = rows[i]; c[j] = cols[i]; s[j] = vals[i];
            }

            float4 a[4];
            #pragma unroll
            for (int j = 0; j < 4; j++)
                a[j] = __ldg((const float4*)(emb + (long)c[j] * DD) + lane);

            #pragma unroll
            for (int j = 0; j < 4; j++) {
                if (j < cnt) {
                    float4 v = make_float4(a[j].x * s[j], a[j].y * s[j],
                                           a[j].z * s[j], a[j].w * s[j]);
                    red_add_v4(user_out + (long)u[j] * DD + lane * 4, v);
                }
            }
        }
    }
}

extern "C" void kernel_launch(void* const* d_in, const int* in_sizes, int n_in,
                              void* d_out, int out_size) {
    const float* emb    = (const float*)d_in[0];
    const int*   ei     = (const int*)d_in[1];
    const int*   et     = (const int*)d_in[2];
    const int*   irows  = (const int*)d_in[3];
    const int*   icols  = (const int*)d_in[4];
    const float* ivals  = (const float*)d_in[5];
    const float* weight = (const float*)d_in[n_in - 1];

    int n_entities = in_sizes[0] / DD;
    int n_edges    = in_sizes[2];
    int nnz        = in_sizes[5];
    int n_rel      = in_sizes[n_in - 1] / DD;
    if (n_rel > MAX_RELS) n_rel = MAX_RELS;

    float* ent_out  = (float*)d_out;
    float* user_out = (float*)d_out + (long)n_entities * DD;

    // Zero output (DMA fill) and counts scratch.
    cudaMemsetAsync(d_out, 0, (size_t)out_size * sizeof(float));
    void* counts_addr = nullptr;
    cudaGetSymbolAddress(&counts_addr, g_counts);
    cudaMemsetAsync(counts_addr, 0, (size_t)n_entities * sizeof(float));

    // Pass 1: counts (int4-vectorized, 4 edges/thread).
    {
        int threads = 256;
        int per_block = threads * 4;
        hgcn_count_kernel<<<(n_edges + per_block - 1) / per_block, threads>>>(ei, n_edges);
    }

    // Fused scatter: one persistent wave, per-SM mixed sections.
    {
        const int SMS = 148;
        const int ROWS = 8;        // 8 blocks of 256 threads per SM (full occ)
        const int EDGE_ROWS = 3;   // 37.5% of blocks ~ edge share of traffic
        int threads = 256;
        hgcn_scatter_kernel<<<SMS * ROWS, threads>>>(
            emb, ei, et, weight, irows, icols, ivals,
            ent_out, user_out, n_edges, n_rel, nnz,
            SMS, EDGE_ROWS, ROWS);
    }
}

// round 13
// speedup vs baseline: 1.1430x; 1.1430x over previous
#include <cuda_runtime.h>

// HGCNLayer: KG scatter-mean + sparse user aggregation.
// Inputs (JAX default config: "int64" arrays are int32):
//  0: entity_emb float32 [N_ENT*128], 1: edge_index int32 [2*E],
//  2: edge_type int32 [E], 3: interact_rows int32 [NNZ],
//  4: interact_cols int32 [NNZ], 5: interact_vals float32 [NNZ],
//  (optional n_users scalar), last: weight float32 [R*128]
// Output: [entity_agg (N_ENT*128) | user_agg (N_USR*128)] float32
//
// Counts-first (inline 1/deg in the edge path; no invert/finalize passes).
// R12 lesson: the scatter kernel is LATENCY-bound (L2 52%, issue 30%), so the
// grid is oversubscribed (2368 blocks -> ~14 resident/SM, smem-capped) and
// both sections run 4 items per warp-iteration with all gathers issued
// before any reduction.

#define DD 128
#define MAX_ENTITIES 100000
#define MAX_RELS 32

__device__ float g_counts[MAX_ENTITIES];

__device__ __forceinline__ void red_add_v4(float* p, float4 v) {
    asm volatile("red.global.add.v4.f32 [%0], {%1, %2, %3, %4};"
                 :: "l"(p), "f"(v.x), "f"(v.y), "f"(v.z), "f"(v.w)
                 : "memory");
}

__device__ __forceinline__ void red_add_f32(float* p, float v) {
    asm volatile("red.global.add.f32 [%0], %1;" :: "l"(p), "f"(v) : "memory");
}

// Pass 1: per-head edge counts. int4-vectorized index load, 4 edges/thread.
__global__ void hgcn_count_kernel(const int* __restrict__ edge_index, int n_edges) {
    int t = blockIdx.x * blockDim.x + threadIdx.x;
    int base = t * 4;
    if (base + 3 < n_edges) {
        int4 h = __ldg((const int4*)(edge_index) + t);
        red_add_f32(&g_counts[h.x], 1.0f);
        red_add_f32(&g_counts[h.y], 1.0f);
        red_add_f32(&g_counts[h.z], 1.0f);
        red_add_f32(&g_counts[h.w], 1.0f);
    } else {
        for (int e = base; e < n_edges; e++)
            red_add_f32(&g_counts[edge_index[e]], 1.0f);
    }
}

// Fused scatter kernel, strided warps, oversubscribed grid.
// Blocks [0, edge_blocks): edges, 4 per warp-iteration, weight in smem.
// Blocks [edge_blocks, ...): users, 4 per warp-iteration.
__global__ void hgcn_scatter_kernel(const float* __restrict__ emb,
                                    const int* __restrict__ edge_index,
                                    const int* __restrict__ edge_type,
                                    const float* __restrict__ weight,
                                    const int* __restrict__ rows,
                                    const int* __restrict__ cols,
                                    const float* __restrict__ vals,
                                    float* __restrict__ ent_out,
                                    float* __restrict__ user_out,
                                    int n_edges, int n_rel, int nnz,
                                    int edge_blocks, int user_blocks) {
    __shared__ float4 sw[MAX_RELS * 32];
    int lane = threadIdx.x & 31;
    int wib  = threadIdx.x >> 5;
    int wpb  = blockDim.x >> 5;

    if (blockIdx.x < edge_blocks) {
        // ---- edge section: 4 edges per warp-iteration ----
        int nw4 = n_rel * 32;
        for (int i = threadIdx.x; i < nw4; i += blockDim.x)
            sw[i] = ((const float4*)weight)[i];
        __syncthreads();

        int warp   = blockIdx.x * wpb + wib;
        int nwarps = edge_blocks * wpb;
        long stride = (long)nwarps * 4;

        for (long base = (long)warp * 4; base < n_edges; base += stride) {
            int cnt = (int)min((long)4, (long)n_edges - base);

            int h[4], t[4], r[4];
            #pragma unroll
            for (int j = 0; j < 4; j++) {
                long e = base + ((j < cnt) ? j : 0);
                h[j] = edge_index[e];
                t[j] = edge_index[n_edges + e];
                r[j] = edge_type[e] - 1;
            }

            // All gathers in flight before any reduction.
            float4 a[4];
            #pragma unroll
            for (int j = 0; j < 4; j++)
                a[j] = __ldg((const float4*)(emb + (long)t[j] * DD) + lane);

            float inv[4];
            #pragma unroll
            for (int j = 0; j < 4; j++)
                inv[j] = __frcp_rn(fmaxf(g_counts[h[j]], 1.0f));

            #pragma unroll
            for (int j = 0; j < 4; j++) {
                if (j < cnt) {
                    float4 b = sw[r[j] * 32 + lane];
                    float4 v = make_float4(a[j].x * b.x * inv[j],
                                           a[j].y * b.y * inv[j],
                                           a[j].z * b.z * inv[j],
                                           a[j].w * b.w * inv[j]);
                    red_add_v4(ent_out + (long)h[j] * DD + lane * 4, v);
                }
            }
        }
    } else {
        // ---- user section: 4 nnz per warp-iteration ----
        int warp   = (blockIdx.x - edge_blocks) * wpb + wib;
        int nwarps = user_blocks * wpb;
        long stride = (long)nwarps * 4;

        for (long base = (long)warp * 4; base < nnz; base += stride) {
            int cnt = (int)min((long)4, (long)nnz - base);

            int   u[4], c[4];
            float s[4];
            #pragma unroll
            for (int j = 0; j < 4; j++) {
                long i = base + ((j < cnt) ? j : 0);
                u[j] = rows[i]; c[j] = cols[i]; s[j] = vals[i];
            }

            float4 a[4];
            #pragma unroll
            for (int j = 0; j < 4; j++)
                a[j] = __ldg((const float4*)(emb + (long)c[j] * DD) + lane);

            #pragma unroll
            for (int j = 0; j < 4; j++) {
                if (j < cnt) {
                    float4 v = make_float4(a[j].x * s[j], a[j].y * s[j],
                                           a[j].z * s[j], a[j].w * s[j]);
                    red_add_v4(user_out + (long)u[j] * DD + lane * 4, v);
                }
            }
        }
    }
}

extern "C" void kernel_launch(void* const* d_in, const int* in_sizes, int n_in,
                              void* d_out, int out_size) {
    const float* emb    = (const float*)d_in[0];
    const int*   ei     = (const int*)d_in[1];
    const int*   et     = (const int*)d_in[2];
    const int*   irows  = (const int*)d_in[3];
    const int*   icols  = (const int*)d_in[4];
    const float* ivals  = (const float*)d_in[5];
    const float* weight = (const float*)d_in[n_in - 1];

    int n_entities = in_sizes[0] / DD;
    int n_edges    = in_sizes[2];
    int nnz        = in_sizes[5];
    int n_rel      = in_sizes[n_in - 1] / DD;
    if (n_rel > MAX_RELS) n_rel = MAX_RELS;

    float* ent_out  = (float*)d_out;
    float* user_out = (float*)d_out + (long)n_entities * DD;

    // Zero output (DMA fill) and counts scratch.
    cudaMemsetAsync(d_out, 0, (size_t)out_size * sizeof(float));
    void* counts_addr = nullptr;
    cudaGetSymbolAddress(&counts_addr, g_counts);
    cudaMemsetAsync(counts_addr, 0, (size_t)n_entities * sizeof(float));

    // Pass 1: counts (int4-vectorized, 4 edges/thread).
    {
        int threads = 256;
        int per_block = threads * 4;
        hgcn_count_kernel<<<(n_edges + per_block - 1) / per_block, threads>>>(ei, n_edges);
    }

    // Fused scatter: oversubscribed grid for latency hiding (~14 blocks/SM
    // resident, smem-capped).
    {
        int threads = 256;        // 8 warps
        int edge_blocks = 1184;   // 8 * 148
        int user_blocks = 1184;
        hgcn_scatter_kernel<<<edge_blocks + user_blocks, threads>>>(
            emb, ei, et, weight, irows, icols, ivals,
            ent_out, user_out, n_edges, n_rel, nnz, edge_blocks, user_blocks);
    }
}